// round 13
// baseline (speedup 1.0000x reference)
#include <cuda_runtime.h>
#include <math.h>

#define T_LEN 32
#define KP    2048
#define CPB   16                       // columns per CTA
#define GPC   16                       // threads per column
#define BLOCK 256
#define GRID  128                      // single wave
#define SETUP_BLOCKS 256

// sp = sqrt(1/32); 0.5/sp^2 = 16 exactly
#define LOG_SP     (-1.7328679513998633f)
#define HALF_L2PI  (0.9189385332046727f)
#define LOG_K      (7.6246189861593985f)
#define C2EXP      (-23.083120654223414f)   // -16 * log2(e)
#define L2E        (1.4426950408889634f)
#define F_INF      (__int_as_float(0x7f800000))

__device__ float g_zs[T_LEN * KP];
__device__ float g_A [T_LEN * KP];
__device__ float g_rb[T_LEN][KP];
__device__ int   g_xmax[T_LEN];   // order-encoded max of r_t
__device__ int   g_cnt [T_LEN];   // producer completion counters (t=0: setup blocks)

__device__ __forceinline__ int   fenc(float f) { int b = __float_as_int(f); return b >= 0 ? b : (b ^ 0x7fffffff); }
__device__ __forceinline__ float fdec(int e)   { return __int_as_float(e >= 0 ? e : (e ^ 0x7fffffff)); }

__device__ __forceinline__ float ex2(float t) {
    float r; asm("ex2.approx.ftz.f32 %0,%1;" : "=f"(r) : "f"(t)); return r;
}

// packed f32x2 ops (sm_103a)
#define F2ADD(o,a,b)   asm("add.rn.f32x2 %0,%1,%2;"    : "=l"(o) : "l"(a), "l"(b))
#define F2MUL(o,a,b)   asm("mul.rn.f32x2 %0,%1,%2;"    : "=l"(o) : "l"(a), "l"(b))
#define F2FMA(o,a,b,c) asm("fma.rn.f32x2 %0,%1,%2,%3;" : "=l"(o) : "l"(a), "l"(b), "l"(c))
__device__ __forceinline__ unsigned long long f2pk(float lo, float hi) {
    unsigned long long r; asm("mov.b64 %0,{%1,%2};" : "=l"(r) : "f"(lo), "f"(hi)); return r;
}
__device__ __forceinline__ void f2un(float& lo, float& hi, unsigned long long v) {
    asm("mov.b64 {%0,%1},%2;" : "=f"(lo), "=f"(hi) : "l"(v));
}

__device__ __forceinline__ int ld_acq(const int* p) {
    int v; asm volatile("ld.acquire.gpu.global.s32 %0,[%1];" : "=r"(v) : "l"(p) : "memory"); return v;
}
__device__ __forceinline__ void red_rel_add(int* p) {
    asm volatile("red.release.gpu.global.add.s32 [%0],1;" :: "l"(p) : "memory");
}
__device__ __forceinline__ void spin_cnt(const int* p, int target) {
    if (threadIdx.x == 0) {
        while (ld_acq(p) < target) __nanosleep(64);
    }
    __syncthreads();
}

__global__ void init_kernel() {
    int i = threadIdx.x;
    if (i < T_LEN) {
        *(volatile int*)&g_xmax[i] = fenc(-F_INF);
        *(volatile int*)&g_cnt[i]  = 0;
    }
}

// Setup: zs, A; blocks 0..7 also produce r0 + publish xmax[0]; ALL blocks count into g_cnt[0].
__global__ void __launch_bounds__(256) setup_kernel(const float* __restrict__ means,
                                                    const float* __restrict__ log_stds,
                                                    const float* __restrict__ eps) {
    __shared__ float red[8];
    int tid = threadIdx.x;
    int idx = blockIdx.x * 256 + tid;              // covers T_LEN*KP exactly
    int t = idx >> 11;
    int k = idx & (KP - 1);
    float mu = means[t];
    float sg = expf(log_stds[t]);
    float z  = fmaf(sg, eps[idx], mu);
    float zq = (z - mu) / sg;
    float lq = fmaf(-0.5f * zq, zq, -logf(sg)) - HALF_L2PI;
    g_zs[idx] = z;
    g_A[idx]  = -LOG_SP - HALF_L2PI - lq;
    if (blockIdx.x < 8) {                          // t == 0 blocks produce r0
        float zz = z * 5.656854249492380f;         // z / sp
        float r0 = fmaf(-0.5f * zz, zz, -LOG_SP) - HALF_L2PI - lq;
        __stcg(&g_rb[0][k], r0);
        float m = r0;
        #pragma unroll
        for (int s = 16; s; s >>= 1)
            m = fmaxf(m, __shfl_xor_sync(0xffffffffu, m, s));
        if ((tid & 31) == 0) red[tid >> 5] = m;
    }
    __syncthreads();
    if (tid == 0) {
        __threadfence();
        if (blockIdx.x < 8) {
            float v = red[0];
            #pragma unroll
            for (int w = 1; w < 8; w++) v = fmaxf(v, red[w]);
            atomicMax(&g_xmax[0], fenc(v));
        }
        red_rel_add(&g_cnt[0]);
    }
}

// One scan step: PDL trigger at top (cascade launch), data-gated via counters; NO grid sync.
__global__ void __launch_bounds__(BLOCK) step_kernel(int t) {
    __shared__ __align__(16) float az[KP];   // -z_{t-1}
    __shared__ __align__(16) float w [KP];   // (r_j - x) * log2e
    __shared__ float cred[CPB];

    const int tid = threadIdx.x;
    const int c   = tid >> 4;                 // column-in-block 0..15
    const int g   = tid & (GPC - 1);
    const int k   = blockIdx.x * CPB + c;

    cudaTriggerProgrammaticLaunchCompletion();       // cascade: successor launches now

    // gate 1: setup fully done (z/A valid). Cheap: single word, usually already set.
    spin_cnt(&g_cnt[0], SETUP_BLOCKS);

    // prefill from setup data
    const float4* z4 = reinterpret_cast<const float4*>(g_zs + (t - 1) * KP);
    float4* az4 = reinterpret_cast<float4*>(az);
    #pragma unroll
    for (int s = 0; s < 2; s++) {
        int f = tid + s * 256;
        float4 v = __ldcg(&z4[f]);
        az4[f] = make_float4(-v.x, -v.y, -v.z, -v.w);
    }
    const float zk = __ldcg(&g_zs[t * KP + k]);
    const float ak = __ldcg(&g_A [t * KP + k]);

    // gate 2: r_{t-1} produced by all its producers
    if (t > 1) spin_cnt(&g_cnt[t - 1], GRID);

    const float x   = fdec(__ldcg(&g_xmax[t - 1]));
    const float nxl = -x * L2E;

    // fold: w = (r - x) * log2e
    const float4* r4 = reinterpret_cast<const float4*>(g_rb[t - 1]);
    float4* w4 = reinterpret_cast<float4*>(w);
    #pragma unroll
    for (int s = 0; s < 2; s++) {
        int f = tid + s * 256;
        float4 rv = __ldcg(&r4[f]);
        w4[f] = make_float4(fmaf(rv.x, L2E, nxl), fmaf(rv.y, L2E, nxl),
                            fmaf(rv.z, L2E, nxl), fmaf(rv.w, L2E, nxl));
    }
    __syncthreads();

    // mainloop: S = sum_j 2^(C2*(zk - zj)^2 + w_j)   (packed f32x2 exponent, MUFU exp)
    const unsigned long long zk2 = f2pk(zk, zk);
    const unsigned long long c2v = f2pk(C2EXP, C2EXP);
    float S0 = 0.0f, S1 = 0.0f;
    #pragma unroll 8
    for (int i = 0; i < KP / (4 * GPC); i++) {       // 32 iters, 4 pairs each
        int f = i * GPC + g;                         // half-warps mirror -> LDS broadcast
        float4 a4 = az4[f];
        float4 wv = w4[f];
        unsigned long long d, m, e;
        float t0, t1, t2, t3;
        F2ADD(d, zk2, f2pk(a4.x, a4.y));
        F2MUL(m, d, c2v);
        F2FMA(e, m, d, f2pk(wv.x, wv.y));
        f2un(t0, t1, e);
        F2ADD(d, zk2, f2pk(a4.z, a4.w));
        F2MUL(m, d, c2v);
        F2FMA(e, m, d, f2pk(wv.z, wv.w));
        f2un(t2, t3, e);
        S0 += ex2(t0); S1 += ex2(t1);
        S0 += ex2(t2); S1 += ex2(t3);
    }
    float S = S0 + S1;
    #pragma unroll
    for (int s = GPC / 2; s; s >>= 1)
        S += __shfl_xor_sync(0xffffffffu, S, s, GPC);

    // epilogue: write r_t, publish CTA max + counter
    if (g == 0) {
        float val = x + ak + logf(fmaxf(S, 1e-37f)) - LOG_K;
        __stcg(&g_rb[t][k], val);
        cred[c] = val;
    }
    __syncthreads();
    if (tid < CPB) {
        float v = cred[tid];
        #pragma unroll
        for (int s = CPB / 2; s; s >>= 1)
            v = fmaxf(v, __shfl_xor_sync(0x0000ffffu, v, s, CPB));
        if (tid == 0) {
            __threadfence();
            atomicMax(&g_xmax[t], fenc(v));
            red_rel_add(&g_cnt[t]);
        }
    }
}

// Final: out = x + y + log(sum_j exp(r_j - x)*exp(L_j - y)) - logK
__global__ void __launch_bounds__(256) final_kernel(float* __restrict__ out) {
    __shared__ float sr[KP];
    __shared__ float sL[KP];
    __shared__ float red[16];
    const int tid  = threadIdx.x;
    const int wid  = tid >> 5;
    const int lane = tid & 31;

    cudaTriggerProgrammaticLaunchCompletion();
    spin_cnt(&g_cnt[T_LEN - 1], GRID);

    const float* __restrict__ zrow = g_zs + (T_LEN - 1) * KP;
    float lr = -F_INF, lL = -F_INF;
    #pragma unroll
    for (int i = 0; i < KP / 256; i++) {
        int j = tid + i * 256;
        float r  = __ldcg(&g_rb[T_LEN - 1][j]);
        float dd = 0.5f - __ldcg(&zrow[j]);
        float Lv = fmaf(-0.5f * dd, dd, -HALF_L2PI);
        sr[j] = r; sL[j] = Lv;
        lr = fmaxf(lr, r);
        lL = fmaxf(lL, Lv);
    }
    #pragma unroll
    for (int m = 16; m; m >>= 1) {
        lr = fmaxf(lr, __shfl_xor_sync(0xffffffffu, lr, m));
        lL = fmaxf(lL, __shfl_xor_sync(0xffffffffu, lL, m));
    }
    if (lane == 0) { red[wid] = lr; red[8 + wid] = lL; }
    __syncthreads();
    float x = red[0], y = red[8];
    #pragma unroll
    for (int w = 1; w < 8; w++) {
        x = fmaxf(x, red[w]);
        y = fmaxf(y, red[8 + w]);
    }

    float S = 0.0f;
    #pragma unroll
    for (int i = 0; i < KP / 256; i++) {
        int j = tid + i * 256;
        S += ex2(((sr[j] - x) + (sL[j] - y)) * L2E);
    }
    #pragma unroll
    for (int m = 16; m; m >>= 1)
        S += __shfl_xor_sync(0xffffffffu, S, m);
    if (lane == 0) red[wid] = S;
    __syncthreads();
    if (tid == 0) {
        float tot = 0.0f;
        #pragma unroll
        for (int w = 0; w < 8; w++) tot += red[w];
        out[0] = x + y + logf(tot) - LOG_K;
    }
}

extern "C" void kernel_launch(void* const* d_in, const int* in_sizes, int n_in,
                              void* d_out, int out_size) {
    const float* means    = (const float*)d_in[0];
    const float* log_stds = (const float*)d_in[1];
    const float* eps      = (const float*)d_in[2];
    float* out = (float*)d_out;

    init_kernel<<<1, 64>>>();                        // full barrier vs next (no PDL attr)

    cudaLaunchAttribute attr[1];
    attr[0].id = cudaLaunchAttributeProgrammaticStreamSerialization;
    attr[0].val.programmaticStreamSerializationAllowed = 1;

    cudaLaunchConfig_t cfgS = {};
    cfgS.gridDim  = dim3(SETUP_BLOCKS, 1, 1);
    cfgS.blockDim = dim3(256, 1, 1);
    cfgS.stream = 0;
    cfgS.attrs = attr;
    cfgS.numAttrs = 1;
    cudaLaunchKernelEx(&cfgS, setup_kernel, means, log_stds, eps);

    cudaLaunchConfig_t cfg = cfgS;
    cfg.gridDim  = dim3(GRID, 1, 1);
    cfg.blockDim = dim3(BLOCK, 1, 1);
    for (int t = 1; t < T_LEN; t++)
        cudaLaunchKernelEx(&cfg, step_kernel, t);

    cudaLaunchConfig_t cfgf = cfg;
    cfgf.gridDim  = dim3(1, 1, 1);
    cfgf.blockDim = dim3(256, 1, 1);
    cudaLaunchKernelEx(&cfgf, final_kernel, out);
}

// round 14
// speedup vs baseline: 1.1970x; 1.1970x over previous
#include <cuda_runtime.h>
#include <math.h>

#define T_LEN 32
#define KP    2048
#define CPB   14                       // columns per CTA
#define GPC   16                       // threads per column
#define BLOCK 224                      // 14 * 16, 7 warps
#define GRID  147                      // 147*14 = 2058 >= 2048; single wave on 148 SMs

// sp = sqrt(1/32); 0.5/sp^2 = 16 exactly
#define LOG_SP     (-1.7328679513998633f)
#define HALF_L2PI  (0.9189385332046727f)
#define LOG_K      (7.6246189861593985f)
#define C2EXP      (-23.083120654223414f)   // -16 * log2(e)
#define L2E        (1.4426950408889634f)
#define LN2        (0.6931471805599453f)
#define F_INF      (__int_as_float(0x7f800000))

__device__ float g_zs[T_LEN * KP];
__device__ float g_A [T_LEN * KP];
__device__ float g_rb[T_LEN][KP];

__device__ __forceinline__ float ex2(float t) {
    float r; asm("ex2.approx.ftz.f32 %0,%1;" : "=f"(r) : "f"(t)); return r;
}
__device__ __forceinline__ float lg2(float t) {
    float r; asm("lg2.approx.f32 %0,%1;" : "=f"(r) : "f"(t)); return r;
}

// Setup, simplified: z-score of proposal == eps, log(std) == log_stds.
// A = 0.5*eps^2 + ls - LOG_SP ;  r0 = A - 16*z^2
__global__ void __launch_bounds__(256) setup_kernel(const float* __restrict__ means,
                                                    const float* __restrict__ log_stds,
                                                    const float* __restrict__ eps) {
    int idx = blockIdx.x * 256 + threadIdx.x;      // grid covers T_LEN*KP exactly
    int t = idx >> 11;
    int k = idx & (KP - 1);
    float ls = log_stds[t];
    float mu = means[t];
    float e  = eps[idx];
    float sg = ex2(ls * L2E);                      // std = exp(log_std)
    float z  = fmaf(sg, e, mu);
    float A  = fmaf(0.5f * e, e, ls) - LOG_SP;
    g_zs[idx] = z;
    g_A[idx]  = A;
    if (t == 0)
        g_rb[0][k] = fmaf(-16.0f * z, z, A);
}

// One scan step (PDL). Post-sync path: r-load + w-fold + reg-max + ONE sync + mainloop.
__global__ void __launch_bounds__(BLOCK) step_kernel(int t) {
    __shared__ __align__(16) float az[KP];   // z_{t-1,j}
    __shared__ __align__(16) float w [KP];   // C2*zj^2 + rj*log2e   (x-free!)
    __shared__ float red[8];

    const int tid  = threadIdx.x;
    const int wid  = tid >> 5;
    const int lane = tid & 31;
    const int c    = tid >> 4;                 // column-in-block 0..13
    const int g    = tid & (GPC - 1);
    int  k   = blockIdx.x * CPB + c;
    bool act = (k < KP);
    if (!act) k = KP - 1;

    cudaTriggerProgrammaticLaunchCompletion();     // successor may launch now

    // ---- pre-sync prologue: setup-owned data only (launch-gated: setup complete) ----
    const float4* __restrict__ z4 = reinterpret_cast<const float4*>(g_zs + (t - 1) * KP);
    float wb[3][4];
    #pragma unroll
    for (int s = 0; s < 3; s++) {
        int f = tid + s * BLOCK;
        if (f < KP / 4) {
            float4 v = z4[f];
            reinterpret_cast<float4*>(az)[f] = v;
            wb[s][0] = C2EXP * v.x * v.x;
            wb[s][1] = C2EXP * v.y * v.y;
            wb[s][2] = C2EXP * v.z * v.z;
            wb[s][3] = C2EXP * v.w * v.w;
        }
    }
    const float zk = g_zs[t * KP + k];
    const float ak = g_A [t * KP + k];

    cudaGridDependencySynchronize();               // wait for r_{t-1}

    // ---- post-sync: load r, fold w (no x needed), max from regs ----
    const float4* __restrict__ r4 = reinterpret_cast<const float4*>(g_rb[t - 1]);
    float lm = -F_INF;
    #pragma unroll
    for (int s = 0; s < 3; s++) {
        int f = tid + s * BLOCK;
        if (f < KP / 4) {
            float4 rv = r4[f];
            reinterpret_cast<float4*>(w)[f] =
                make_float4(fmaf(rv.x, L2E, wb[s][0]), fmaf(rv.y, L2E, wb[s][1]),
                            fmaf(rv.z, L2E, wb[s][2]), fmaf(rv.w, L2E, wb[s][3]));
            lm = fmaxf(lm, fmaxf(fmaxf(rv.x, rv.y), fmaxf(rv.z, rv.w)));
        }
    }
    #pragma unroll
    for (int s = 16; s; s >>= 1)
        lm = fmaxf(lm, __shfl_xor_sync(0xffffffffu, lm, s));
    if (lane == 0) red[wid] = lm;
    __syncthreads();                               // covers az, w, red
    float x = red[0];
    #pragma unroll
    for (int ww = 1; ww < BLOCK / 32; ww++) x = fmaxf(x, red[ww]);

    // ---- mainloop: S = sum_j 2^( fmaf(m2, zj, w_j) + qk ) ----
    const float qk = fmaf(-x, L2E, C2EXP * zk * zk);
    const float m2 = -2.0f * C2EXP * zk;
    const float2* __restrict__ az2 = reinterpret_cast<const float2*>(az);
    const float2* __restrict__ w2  = reinterpret_cast<const float2*>(w);
    float S0 = 0.0f, S1 = 0.0f;
    #pragma unroll 8
    for (int i = 0; i < KP / (2 * GPC); i++) {
        int f = i * GPC + g;                       // half-warps mirror -> LDS broadcast
        float2 a = az2[f];
        float2 v = w2[f];
        S0 += ex2(fmaf(m2, a.x, v.x) + qk);
        S1 += ex2(fmaf(m2, a.y, v.y) + qk);
    }
    float S = S0 + S1;
    #pragma unroll
    for (int s = GPC / 2; s; s >>= 1)
        S += __shfl_xor_sync(0xffffffffu, S, s, GPC);

    if (g == 0 && act)
        g_rb[t][k] = x + ak + lg2(fmaxf(S, 1e-37f)) * LN2 - LOG_K;
}

// Final: out = x + y + log(sum_j exp(r_j - x)*exp(L_j - y)) - logK
__global__ void __launch_bounds__(256) final_kernel(float* __restrict__ out) {
    __shared__ float sr[KP];
    __shared__ float sL[KP];
    __shared__ float red[16];
    const int tid  = threadIdx.x;
    const int wid  = tid >> 5;
    const int lane = tid & 31;

    cudaGridDependencySynchronize();

    const float* __restrict__ zrow = g_zs + (T_LEN - 1) * KP;
    const float* __restrict__ rin  = g_rb[T_LEN - 1];
    float lr = -F_INF, lL = -F_INF;
    #pragma unroll
    for (int i = 0; i < KP / 256; i++) {
        int j = tid + i * 256;
        float r  = rin[j];
        float dd = 0.5f - zrow[j];
        float Lv = fmaf(-0.5f * dd, dd, -HALF_L2PI);
        sr[j] = r; sL[j] = Lv;
        lr = fmaxf(lr, r);
        lL = fmaxf(lL, Lv);
    }
    #pragma unroll
    for (int m = 16; m; m >>= 1) {
        lr = fmaxf(lr, __shfl_xor_sync(0xffffffffu, lr, m));
        lL = fmaxf(lL, __shfl_xor_sync(0xffffffffu, lL, m));
    }
    if (lane == 0) { red[wid] = lr; red[8 + wid] = lL; }
    __syncthreads();
    float x = red[0], y = red[8];
    #pragma unroll
    for (int w = 1; w < 8; w++) {
        x = fmaxf(x, red[w]);
        y = fmaxf(y, red[8 + w]);
    }

    float S = 0.0f;
    #pragma unroll
    for (int i = 0; i < KP / 256; i++) {
        int j = tid + i * 256;
        S += ex2(((sr[j] - x) + (sL[j] - y)) * L2E);
    }
    #pragma unroll
    for (int m = 16; m; m >>= 1)
        S += __shfl_xor_sync(0xffffffffu, S, m);
    if (lane == 0) red[wid] = S;
    __syncthreads();
    if (tid == 0) {
        float tot = 0.0f;
        #pragma unroll
        for (int w = 0; w < 8; w++) tot += red[w];
        out[0] = x + y + logf(tot) - LOG_K;
    }
}

extern "C" void kernel_launch(void* const* d_in, const int* in_sizes, int n_in,
                              void* d_out, int out_size) {
    const float* means    = (const float*)d_in[0];
    const float* log_stds = (const float*)d_in[1];
    const float* eps      = (const float*)d_in[2];
    float* out = (float*)d_out;

    setup_kernel<<<(T_LEN * KP) / 256, 256>>>(means, log_stds, eps);

    cudaLaunchAttribute attr[1];
    attr[0].id = cudaLaunchAttributeProgrammaticStreamSerialization;
    attr[0].val.programmaticStreamSerializationAllowed = 1;

    cudaLaunchConfig_t cfg = {};
    cfg.gridDim  = dim3(GRID, 1, 1);
    cfg.blockDim = dim3(BLOCK, 1, 1);
    cfg.dynamicSmemBytes = 0;
    cfg.stream = 0;
    cfg.attrs = attr;
    cfg.numAttrs = 1;

    for (int t = 1; t < T_LEN; t++)
        cudaLaunchKernelEx(&cfg, step_kernel, t);

    cudaLaunchConfig_t cfgf = cfg;
    cfgf.gridDim  = dim3(1, 1, 1);
    cfgf.blockDim = dim3(256, 1, 1);
    cudaLaunchKernelEx(&cfgf, final_kernel, out);
}

// round 15
// speedup vs baseline: 1.4756x; 1.2328x over previous
#include <cuda_runtime.h>
#include <math.h>

#define T_LEN 32
#define KP    2048
#define CPB   16                       // columns per CTA
#define GPC   16                       // threads per column
#define BLOCK 256
#define GRID  128                      // 128*16 = 2048 columns; best measured PDL shape

// sp = sqrt(1/32); 0.5/sp^2 = 16 exactly
#define LOG_SP     (-1.7328679513998633f)
#define HALF_L2PI  (0.9189385332046727f)
#define LOG_K      (7.6246189861593985f)
#define C2EXP      (-23.083120654223414f)   // -16 * log2(e)
#define L2E        (1.4426950408889634f)
#define LN2        (0.6931471805599453f)
#define F_INF      (__int_as_float(0x7f800000))

__device__ float g_zs[T_LEN * KP];
__device__ float g_A [T_LEN * KP];
__device__ float g_rb[T_LEN][KP];

__device__ __forceinline__ float ex2(float t) {
    float r; asm("ex2.approx.ftz.f32 %0,%1;" : "=f"(r) : "f"(t)); return r;
}
__device__ __forceinline__ float lg2(float t) {
    float r; asm("lg2.approx.f32 %0,%1;" : "=f"(r) : "f"(t)); return r;
}

// Setup (simplified): proposal z-score == eps, log(std) == log_stds.
// A = 0.5*eps^2 + ls - LOG_SP ;  r0 = A - 16*z^2
__global__ void __launch_bounds__(256) setup_kernel(const float* __restrict__ means,
                                                    const float* __restrict__ log_stds,
                                                    const float* __restrict__ eps) {
    int idx = blockIdx.x * 256 + threadIdx.x;      // grid covers T_LEN*KP exactly
    int t = idx >> 11;
    int k = idx & (KP - 1);
    float ls = log_stds[t];
    float mu = means[t];
    float e  = eps[idx];
    float sg = ex2(ls * L2E);                      // std = exp(log_std)
    float z  = fmaf(sg, e, mu);
    float A  = fmaf(0.5f * e, e, ls) - LOG_SP;
    g_zs[idx] = z;
    g_A[idx]  = A;
    if (t == 0)
        g_rb[0][k] = fmaf(-16.0f * z, z, A);
}

// One scan step (PDL). Post-sync path: r-load + x-free w-fold + reg-max + ONE sync + mainloop.
__global__ void __launch_bounds__(BLOCK) step_kernel(int t) {
    __shared__ __align__(16) float az[KP];   // z_{t-1,j}
    __shared__ __align__(16) float w [KP];   // C2*zj^2 + rj*log2e   (x-free)
    __shared__ float red[8];

    const int tid  = threadIdx.x;
    const int wid  = tid >> 5;
    const int lane = tid & 31;
    const int c    = tid >> 4;                 // column-in-block 0..15
    const int g    = tid & (GPC - 1);
    const int k    = blockIdx.x * CPB + c;     // always < KP

    cudaTriggerProgrammaticLaunchCompletion();     // successor may launch now

    // ---- pre-sync prologue: setup-owned data only ----
    const float4* __restrict__ z4 = reinterpret_cast<const float4*>(g_zs + (t - 1) * KP);
    float wb[2][4];
    #pragma unroll
    for (int s = 0; s < 2; s++) {
        int f = tid + s * BLOCK;
        float4 v = z4[f];
        reinterpret_cast<float4*>(az)[f] = v;
        wb[s][0] = C2EXP * v.x * v.x;
        wb[s][1] = C2EXP * v.y * v.y;
        wb[s][2] = C2EXP * v.z * v.z;
        wb[s][3] = C2EXP * v.w * v.w;
    }
    const float zk = g_zs[t * KP + k];
    const float ak = g_A [t * KP + k];

    cudaGridDependencySynchronize();               // wait for r_{t-1}

    // ---- post-sync: load r, fold w (no x dependency), reg-side max ----
    const float4* __restrict__ r4 = reinterpret_cast<const float4*>(g_rb[t - 1]);
    float lm = -F_INF;
    #pragma unroll
    for (int s = 0; s < 2; s++) {
        int f = tid + s * BLOCK;
        float4 rv = r4[f];
        reinterpret_cast<float4*>(w)[f] =
            make_float4(fmaf(rv.x, L2E, wb[s][0]), fmaf(rv.y, L2E, wb[s][1]),
                        fmaf(rv.z, L2E, wb[s][2]), fmaf(rv.w, L2E, wb[s][3]));
        lm = fmaxf(lm, fmaxf(fmaxf(rv.x, rv.y), fmaxf(rv.z, rv.w)));
    }
    #pragma unroll
    for (int s = 16; s; s >>= 1)
        lm = fmaxf(lm, __shfl_xor_sync(0xffffffffu, lm, s));
    if (lane == 0) red[wid] = lm;
    __syncthreads();                               // covers az, w, red
    float x = red[0];
    #pragma unroll
    for (int ww = 1; ww < 8; ww++) x = fmaxf(x, red[ww]);

    // ---- mainloop: S = sum_j 2^( fmaf(m2, zj, w_j) + qk ) ----
    const float qk = fmaf(-x, L2E, C2EXP * zk * zk);
    const float m2 = -2.0f * C2EXP * zk;
    const float2* __restrict__ az2 = reinterpret_cast<const float2*>(az);
    const float2* __restrict__ w2  = reinterpret_cast<const float2*>(w);
    float S0 = 0.0f, S1 = 0.0f;
    #pragma unroll 8
    for (int i = 0; i < KP / (2 * GPC); i++) {
        int f = i * GPC + g;                       // half-warps mirror -> LDS broadcast
        float2 a = az2[f];
        float2 v = w2[f];
        S0 += ex2(fmaf(m2, a.x, v.x) + qk);
        S1 += ex2(fmaf(m2, a.y, v.y) + qk);
    }
    float S = S0 + S1;
    #pragma unroll
    for (int s = GPC / 2; s; s >>= 1)
        S += __shfl_xor_sync(0xffffffffu, S, s, GPC);

    if (g == 0)
        g_rb[t][k] = x + ak + lg2(fmaxf(S, 1e-37f)) * LN2 - LOG_K;
}

// Final: out = x + y + log(sum_j exp(r_j - x)*exp(L_j - y)) - logK
__global__ void __launch_bounds__(256) final_kernel(float* __restrict__ out) {
    __shared__ float sr[KP];
    __shared__ float sL[KP];
    __shared__ float red[16];
    const int tid  = threadIdx.x;
    const int wid  = tid >> 5;
    const int lane = tid & 31;

    cudaGridDependencySynchronize();

    const float* __restrict__ zrow = g_zs + (T_LEN - 1) * KP;
    const float* __restrict__ rin  = g_rb[T_LEN - 1];
    float lr = -F_INF, lL = -F_INF;
    #pragma unroll
    for (int i = 0; i < KP / 256; i++) {
        int j = tid + i * 256;
        float r  = rin[j];
        float dd = 0.5f - zrow[j];
        float Lv = fmaf(-0.5f * dd, dd, -HALF_L2PI);
        sr[j] = r; sL[j] = Lv;
        lr = fmaxf(lr, r);
        lL = fmaxf(lL, Lv);
    }
    #pragma unroll
    for (int m = 16; m; m >>= 1) {
        lr = fmaxf(lr, __shfl_xor_sync(0xffffffffu, lr, m));
        lL = fmaxf(lL, __shfl_xor_sync(0xffffffffu, lL, m));
    }
    if (lane == 0) { red[wid] = lr; red[8 + wid] = lL; }
    __syncthreads();
    float x = red[0], y = red[8];
    #pragma unroll
    for (int w = 1; w < 8; w++) {
        x = fmaxf(x, red[w]);
        y = fmaxf(y, red[8 + w]);
    }

    float S = 0.0f;
    #pragma unroll
    for (int i = 0; i < KP / 256; i++) {
        int j = tid + i * 256;
        S += ex2(((sr[j] - x) + (sL[j] - y)) * L2E);
    }
    #pragma unroll
    for (int m = 16; m; m >>= 1)
        S += __shfl_xor_sync(0xffffffffu, S, m);
    if (lane == 0) red[wid] = S;
    __syncthreads();
    if (tid == 0) {
        float tot = 0.0f;
        #pragma unroll
        for (int w = 0; w < 8; w++) tot += red[w];
        out[0] = x + y + logf(tot) - LOG_K;
    }
}

extern "C" void kernel_launch(void* const* d_in, const int* in_sizes, int n_in,
                              void* d_out, int out_size) {
    const float* means    = (const float*)d_in[0];
    const float* log_stds = (const float*)d_in[1];
    const float* eps      = (const float*)d_in[2];
    float* out = (float*)d_out;

    setup_kernel<<<(T_LEN * KP) / 256, 256>>>(means, log_stds, eps);

    cudaLaunchAttribute attr[1];
    attr[0].id = cudaLaunchAttributeProgrammaticStreamSerialization;
    attr[0].val.programmaticStreamSerializationAllowed = 1;

    cudaLaunchConfig_t cfg = {};
    cfg.gridDim  = dim3(GRID, 1, 1);
    cfg.blockDim = dim3(BLOCK, 1, 1);
    cfg.dynamicSmemBytes = 0;
    cfg.stream = 0;
    cfg.attrs = attr;
    cfg.numAttrs = 1;

    for (int t = 1; t < T_LEN; t++)
        cudaLaunchKernelEx(&cfg, step_kernel, t);

    cudaLaunchConfig_t cfgf = cfg;
    cfgf.gridDim  = dim3(1, 1, 1);
    cfgf.blockDim = dim3(256, 1, 1);
    cudaLaunchKernelEx(&cfgf, final_kernel, out);
}

// round 16
// speedup vs baseline: 1.5660x; 1.0613x over previous
#include <cuda_runtime.h>
#include <math.h>

#define T_LEN 32
#define KP    2048
#define CPB   16                       // columns per CTA
#define GPC   16                       // threads per column
#define BLOCK 256
#define GRID  128                      // best measured PDL shape

// sp = sqrt(1/32); 0.5/sp^2 = 16 exactly
#define LOG_SP     (-1.7328679513998633f)
#define HALF_L2PI  (0.9189385332046727f)
#define LOG_K      (7.6246189861593985f)
#define C2EXP      (-23.083120654223414f)   // -16 * log2(e)
#define L2E        (1.4426950408889634f)
#define LN2        (0.6931471805599453f)
#define F_INF      (__int_as_float(0x7f800000))

__device__ float g_zs[T_LEN * KP];
__device__ float g_A [T_LEN * KP];
__device__ float g_w [T_LEN][KP];     // w_t[j] = C2*z_{t,j}^2 + r_t[j]*log2e

__device__ __forceinline__ float ex2(float t) {
    float r; asm("ex2.approx.ftz.f32 %0,%1;" : "=f"(r) : "f"(t)); return r;
}
__device__ __forceinline__ float lg2(float t) {
    float r; asm("lg2.approx.f32 %0,%1;" : "=f"(r) : "f"(t)); return r;
}

// Setup: z = mu + std*eps; A = 0.5*eps^2 + ls - LOG_SP; w0 = (A - 32 z^2)*log2e
__global__ void __launch_bounds__(256) setup_kernel(const float* __restrict__ means,
                                                    const float* __restrict__ log_stds,
                                                    const float* __restrict__ eps) {
    int idx = blockIdx.x * 256 + threadIdx.x;      // grid covers T_LEN*KP exactly
    int t = idx >> 11;
    int k = idx & (KP - 1);
    float ls = log_stds[t];
    float mu = means[t];
    float e  = eps[idx];
    float sg = ex2(ls * L2E);                      // std = exp(log_std)
    float z  = fmaf(sg, e, mu);
    float A  = fmaf(0.5f * e, e, ls) - LOG_SP;
    g_zs[idx] = z;
    g_A[idx]  = A;
    if (t == 0)
        g_w[0][k] = (fmaf(-32.0f * z, z, A)) * L2E;
}

// One scan step (PDL). Post-sync path: w-load -> STS -> bar -> MUFU mainloop. No reductions.
__global__ void __launch_bounds__(BLOCK) step_kernel(int t) {
    __shared__ __align__(16) float az[KP];   // z_{t-1,j}
    __shared__ __align__(16) float sw[KP];   // w_{t-1,j}

    const int tid = threadIdx.x;
    const int c   = tid >> 4;                 // column-in-block 0..15
    const int g   = tid & (GPC - 1);
    const int k   = blockIdx.x * CPB + c;     // always < KP

    cudaTriggerProgrammaticLaunchCompletion();     // successor may launch now

    // ---- pre-sync prologue: setup-owned data only ----
    const float4* __restrict__ z4 = reinterpret_cast<const float4*>(g_zs + (t - 1) * KP);
    #pragma unroll
    for (int s = 0; s < 2; s++) {
        int f = tid + s * BLOCK;
        reinterpret_cast<float4*>(az)[f] = z4[f];
    }
    const float zk = g_zs[t * KP + k];
    const float ak = g_A [t * KP + k];
    const float qk = C2EXP * zk * zk;
    const float m2 = -2.0f * C2EXP * zk;
    const float ck = fmaf(ak - LOG_K, L2E, qk);    // w_out = ck + lg2(S)

    cudaGridDependencySynchronize();               // wait for w_{t-1}

    // ---- post-sync: copy w row into SMEM ----
    const float4* __restrict__ w4 = reinterpret_cast<const float4*>(g_w[t - 1]);
    #pragma unroll
    for (int s = 0; s < 2; s++) {
        int f = tid + s * BLOCK;
        reinterpret_cast<float4*>(sw)[f] = w4[f];
    }
    __syncthreads();

    // ---- mainloop: S = sum_j 2^( C2*(zk-zj)^2 + r_j*log2e ) = sum_j 2^(fmaf(m2,zj,wj)+qk) ----
    const float2* __restrict__ az2 = reinterpret_cast<const float2*>(az);
    const float2* __restrict__ w2  = reinterpret_cast<const float2*>(sw);
    float S0 = 0.0f, S1 = 0.0f;
    #pragma unroll 8
    for (int i = 0; i < KP / (2 * GPC); i++) {
        int f = i * GPC + g;                       // half-warps mirror -> LDS broadcast
        float2 a = az2[f];
        float2 v = w2[f];
        S0 += ex2(fmaf(m2, a.x, v.x) + qk);
        S1 += ex2(fmaf(m2, a.y, v.y) + qk);
    }
    float S = S0 + S1;
    #pragma unroll
    for (int s = GPC / 2; s; s >>= 1)
        S += __shfl_xor_sync(0xffffffffu, S, s, GPC);

    if (g == 0)
        g_w[t][k] = ck + lg2(fmaxf(S, 1e-37f));
}

// Final: out = log( sum_j exp(r_j + L_j) ) - logK, computed unshifted in 2^-domain.
// r_j = (w_j - C2*z_j^2)*ln2 ; terms = 2^( w_j - C2*z_j^2 + L_j*log2e )
__global__ void __launch_bounds__(256) final_kernel(float* __restrict__ out) {
    __shared__ __align__(16) float sb[KP];   // -C2*z^2 + L*log2e  (pre-sync part)
    __shared__ float red[8];
    const int tid  = threadIdx.x;
    const int wid  = tid >> 5;
    const int lane = tid & 31;

    cudaTriggerProgrammaticLaunchCompletion();

    // pre-sync: z-derived part of the exponent
    const float* __restrict__ zrow = g_zs + (T_LEN - 1) * KP;
    #pragma unroll
    for (int i = 0; i < KP / 256; i++) {
        int j = tid + i * 256;
        float z  = zrow[j];
        float dd = 0.5f - z;
        float Lv = fmaf(-0.5f * dd, dd, -HALF_L2PI);   // logN(0.5; z, 1)
        sb[j] = fmaf(Lv, L2E, -C2EXP * z * z);
    }

    cudaGridDependencySynchronize();

    const float* __restrict__ win = g_w[T_LEN - 1];
    float S = 0.0f;
    #pragma unroll
    for (int i = 0; i < KP / 256; i++) {
        int j = tid + i * 256;
        S += ex2(win[j] + sb[j]);
    }
    #pragma unroll
    for (int m = 16; m; m >>= 1)
        S += __shfl_xor_sync(0xffffffffu, S, m);
    if (lane == 0) red[wid] = S;
    __syncthreads();
    if (tid == 0) {
        float tot = 0.0f;
        #pragma unroll
        for (int w = 0; w < 8; w++) tot += red[w];
        out[0] = logf(tot) - LOG_K;
    }
}

extern "C" void kernel_launch(void* const* d_in, const int* in_sizes, int n_in,
                              void* d_out, int out_size) {
    const float* means    = (const float*)d_in[0];
    const float* log_stds = (const float*)d_in[1];
    const float* eps      = (const float*)d_in[2];
    float* out = (float*)d_out;

    setup_kernel<<<(T_LEN * KP) / 256, 256>>>(means, log_stds, eps);

    cudaLaunchAttribute attr[1];
    attr[0].id = cudaLaunchAttributeProgrammaticStreamSerialization;
    attr[0].val.programmaticStreamSerializationAllowed = 1;

    cudaLaunchConfig_t cfg = {};
    cfg.gridDim  = dim3(GRID, 1, 1);
    cfg.blockDim = dim3(BLOCK, 1, 1);
    cfg.dynamicSmemBytes = 0;
    cfg.stream = 0;
    cfg.attrs = attr;
    cfg.numAttrs = 1;

    for (int t = 1; t < T_LEN; t++)
        cudaLaunchKernelEx(&cfg, step_kernel, t);

    cudaLaunchConfig_t cfgf = cfg;
    cfgf.gridDim  = dim3(1, 1, 1);
    cfgf.blockDim = dim3(256, 1, 1);
    cudaLaunchKernelEx(&cfgf, final_kernel, out);
}